// round 5
// baseline (speedup 1.0000x reference)
#include <cuda_runtime.h>
#include <cuda_bf16.h>
#include <math.h>
#include <stdint.h>

// Problem constants
#define L_     128
#define CTX_   896
#define T_     1024
#define STATE_ 3072
#define S_     4096
#define HID_   4096
#define HQ_    32
#define HKV_   8
#define D_     128
#define EPS_   1e-6f
#define SCALE_ 0.08838834764831845f   // 128^-0.5

// GEMM tiling
#define BM 128
#define BN 128
#define BK 32
#define GSTR 40                        // bf16 smem row stride in halves (80B)
#define STAGE_HALVES ((BM*2 + BN*2) * GSTR)          // aHi,aLo,bHi,bLo = 20480
#define GEMM_SMEM (2 * STAGE_HALVES * 2)             // 2 stages -> 81920 bytes

// ---------------- device scratch ----------------
__device__ float g_c[T_ * HID_];                 // concat(x_ctx, x)
__device__ float g_q[L_ * HQ_ * D_];             // raw q projection
__device__ float g_qf[HQ_ * L_ * D_];            // normed+roped q (H,L,D)
__device__ float g_kraw[T_ * HKV_ * D_];         // raw k projection
__device__ float g_vraw[T_ * HKV_ * D_];         // raw v projection
__device__ float g_kfull[HKV_ * S_ * D_];        // full K (cache+new) (H,S,D)
__device__ float g_vt[HKV_ * D_ * S_];           // full V transposed (H,D,S)
__device__ float g_scores[(size_t)HQ_ * L_ * S_];// scores / probs
__device__ float g_o[L_ * HQ_ * D_];             // attention output (L, HQ*D)
__device__ float g_part[4 * 1024 * 1024];        // split-K partials (16MB)

// ---------------- helpers ----------------
__device__ __forceinline__ void ldm_x4(uint32_t (&r)[4], uint32_t addr) {
  asm volatile("ldmatrix.sync.aligned.m8n8.x4.shared.b16 {%0,%1,%2,%3}, [%4];\n"
    : "=r"(r[0]), "=r"(r[1]), "=r"(r[2]), "=r"(r[3]) : "r"(addr));
}
__device__ __forceinline__ void mma16816(float (&d)[4], const uint32_t (&a)[4],
                                         uint32_t b0, uint32_t b1) {
  asm volatile("mma.sync.aligned.m16n8k16.row.col.f32.bf16.bf16.f32 "
    "{%0,%1,%2,%3},{%4,%5,%6,%7},{%8,%9},{%0,%1,%2,%3};\n"
    : "+f"(d[0]), "+f"(d[1]), "+f"(d[2]), "+f"(d[3])
    : "r"(a[0]), "r"(a[1]), "r"(a[2]), "r"(a[3]), "r"(b0), "r"(b1));
}
// convert float4 -> hi bf16x2 pair + lo bf16x2 pair, store to smem
__device__ __forceinline__ void cvt_store(__nv_bfloat16* hi, __nv_bfloat16* lo, float4 v) {
  __nv_bfloat162 h01 = __floats2bfloat162_rn(v.x, v.y);
  __nv_bfloat162 h23 = __floats2bfloat162_rn(v.z, v.w);
  *(__nv_bfloat162*)(hi)     = h01;
  *(__nv_bfloat162*)(hi + 2) = h23;
  *(__nv_bfloat162*)(lo) = __floats2bfloat162_rn(
      v.x - __bfloat162float(h01.x), v.y - __bfloat162float(h01.y));
  *(__nv_bfloat162*)(lo + 2) = __floats2bfloat162_rn(
      v.z - __bfloat162float(h23.x), v.w - __bfloat162float(h23.y));
}

// ---------------- concat c = [x_ctx; x] ----------------
__global__ void __launch_bounds__(256) concat_c(
    const float* __restrict__ xc, const float* __restrict__ x, float* __restrict__ c) {
  int i = blockIdx.x * 256 + threadIdx.x;
  const int CV = CTX_ * HID_ / 4;
  float4 v = (i < CV) ? ((const float4*)xc)[i] : ((const float4*)x)[i - CV];
  ((float4*)c)[i] = v;
}

// ============ batched split-bf16 tensor-core GEMM with split-K ============
// z = b*KS + ks.  C[b][M][N] = A[b][M][K] * B[b>>bshift][N][K]^T
// KS==1: write C + b*batchC.  KS>1: write partials C + z*batchC (dense).
__global__ void __launch_bounds__(256) gemm4(
    const float* __restrict__ A, int lda, long long batchA,
    const float* __restrict__ B, int ldb, long long batchB, int bshift,
    float* __restrict__ C, int ldc, long long batchC,
    int K, int KS)
{
  extern __shared__ __nv_bfloat16 sm[];
  const int tid = threadIdx.x, lane = tid & 31, wid = tid >> 5;
  const int wm = wid & 3, wn = wid >> 2;     // 4x2 warps, warp tile 32x64
  const int m0 = blockIdx.y * BM, n0 = blockIdx.x * BN;
  const int b = blockIdx.z / KS, ks = blockIdx.z - b * KS;
  const int Kc = K / KS, kbase = ks * Kc, iters = Kc / BK;

  const int lrow = tid >> 3, lcol = (tid & 7) << 2;
  const float* Ag = A + (long long)b * batchA + (size_t)(m0 + lrow) * lda + kbase + lcol;
  const float* Bg = B + (long long)(b >> bshift) * batchB + (size_t)(n0 + lrow) * ldb + kbase + lcol;

  float acc[2][8][4];
#pragma unroll
  for (int i = 0; i < 2; i++)
#pragma unroll
    for (int j = 0; j < 8; j++)
#pragma unroll
      for (int q = 0; q < 4; q++) acc[i][j][q] = 0.f;

  const uint32_t smB = (uint32_t)__cvta_generic_to_shared(sm);
  const int aHiOff = 0, aLoOff = BM * GSTR;
  const int bHiOff = 2 * BM * GSTR, bLoOff = 2 * BM * GSTR + BN * GSTR;

  const int a_r = lane & 15, a_c = (lane & 16) >> 1;
  const int b_r = (lane & 7) | ((lane & 16) >> 1), b_c = lane & 8;

  float4 ra[4], rb[4];
  // prologue: load iter0
#pragma unroll
  for (int j = 0; j < 4; j++) ra[j] = *(const float4*)(Ag + (size_t)(32 * j) * lda);
#pragma unroll
  for (int j = 0; j < 4; j++) rb[j] = *(const float4*)(Bg + (size_t)(32 * j) * ldb);

  for (int it = 0; it < iters; it++) {
    const int s = it & 1;
    __nv_bfloat16* st = sm + s * STAGE_HALVES;
    // convert + store current regs -> stage s
#pragma unroll
    for (int j = 0; j < 4; j++) {
      int off = (lrow + 32 * j) * GSTR + lcol;
      cvt_store(st + aHiOff + off, st + aLoOff + off, ra[j]);
      cvt_store(st + bHiOff + off, st + bLoOff + off, rb[j]);
    }
    __syncthreads();
    // prefetch next iter into regs (overlaps MMA below)
    if (it + 1 < iters) {
      const float* An = Ag + (it + 1) * BK;
      const float* Bn = Bg + (it + 1) * BK;
#pragma unroll
      for (int j = 0; j < 4; j++) ra[j] = *(const float4*)(An + (size_t)(32 * j) * lda);
#pragma unroll
      for (int j = 0; j < 4; j++) rb[j] = *(const float4*)(Bn + (size_t)(32 * j) * ldb);
    }
    // MMA on stage s
    uint32_t sb = smB + s * STAGE_HALVES * 2;
#pragma unroll
    for (int k16 = 0; k16 < BK; k16 += 16) {
      uint32_t aH[2][4], aL[2][4];
#pragma unroll
      for (int mi = 0; mi < 2; mi++) {
        uint32_t ro = (uint32_t)(((wm * 32 + mi * 16 + a_r) * GSTR + k16 + a_c) * 2);
        ldm_x4(aH[mi], sb + aHiOff * 2 + ro);
        ldm_x4(aL[mi], sb + aLoOff * 2 + ro);
      }
#pragma unroll
      for (int g = 0; g < 4; g++) {
        uint32_t bH[4], bL[4];
        uint32_t ro = (uint32_t)(((wn * 64 + g * 16 + b_r) * GSTR + k16 + b_c) * 2);
        ldm_x4(bH, sb + bHiOff * 2 + ro);
        ldm_x4(bL, sb + bLoOff * 2 + ro);
#pragma unroll
        for (int mi = 0; mi < 2; mi++)
#pragma unroll
          for (int sub = 0; sub < 2; sub++) {
            int ni = g * 2 + sub, rr = sub * 2;
            mma16816(acc[mi][ni], aH[mi], bH[rr], bH[rr + 1]);
            mma16816(acc[mi][ni], aH[mi], bL[rr], bL[rr + 1]);
            mma16816(acc[mi][ni], aL[mi], bH[rr], bH[rr + 1]);
          }
      }
    }
    __syncthreads();
  }

  // epilogue
  float* Cb = (KS == 1) ? C + (long long)b * batchC : C + (long long)blockIdx.z * batchC;
  const int rb8 = lane >> 2, cb2 = (lane & 3) << 1;
#pragma unroll
  for (int mi = 0; mi < 2; mi++)
#pragma unroll
    for (int ni = 0; ni < 8; ni++) {
      int row = m0 + wm * 32 + mi * 16 + rb8;
      int col = n0 + wn * 64 + ni * 8 + cb2;
      *(float2*)(Cb + (long long)row * ldc + col)       = make_float2(acc[mi][ni][0], acc[mi][ni][1]);
      *(float2*)(Cb + (long long)(row + 8) * ldc + col) = make_float2(acc[mi][ni][2], acc[mi][ni][3]);
    }
}

// ---------------- split-K reduction ----------------
__global__ void __launch_bounds__(256) reduce_ks(
    const float* __restrict__ Pt, float* __restrict__ out,
    int ldc, long long batchC, int M, int N, int KS) {
  long long i4 = (long long)blockIdx.x * 256 + threadIdx.x;
  int perB = M * (N >> 2);
  int b = (int)(i4 / perB);
  int rem = (int)(i4 - (long long)b * perB);
  int m = rem / (N >> 2), n4 = rem - m * (N >> 2);
  const float4* base = (const float4*)Pt + (long long)b * KS * perB + rem;
  float4 s = base[0];
  for (int k = 1; k < KS; k++) {
    float4 v = base[(long long)k * perB];
    s.x += v.x; s.y += v.y; s.z += v.z; s.w += v.w;
  }
  *(float4*)(out + (long long)b * batchC + (long long)m * ldc + (n4 << 2)) = s;
}

// ---------------- fused ane-norm + RoPE ----------------
__global__ void __launch_bounds__(128) norm_rope(
    const float* __restrict__ src, const float* __restrict__ w,
    const float* __restrict__ cs, const float* __restrict__ sn,
    float* __restrict__ dst, int NH, int NR,
    float* __restrict__ dst2, int NR2) {
  int r = blockIdx.x * 4 + (threadIdx.x >> 5);
  int lane = threadIdx.x & 31;
  int row = r / NH, h = r - row * NH;
  float4 v = ((const float4*)(src + (size_t)r * D_))[lane];
  float s = v.x + v.y + v.z + v.w;
#pragma unroll
  for (int o = 16; o; o >>= 1) s += __shfl_xor_sync(0xffffffffu, s, o);
  float mean = s * (1.0f / D_);
  float4 c = make_float4(v.x - mean, v.y - mean, v.z - mean, v.w - mean);
  float q2 = c.x * c.x + c.y * c.y + c.z * c.z + c.w * c.w;
#pragma unroll
  for (int o = 16; o; o >>= 1) q2 += __shfl_xor_sync(0xffffffffu, q2, o);
  float inv = rsqrtf(q2 * (1.0f / D_) + EPS_);
  float4 wv = ((const float4*)w)[lane];
  float4 n = make_float4(c.x * inv * wv.x, c.y * inv * wv.y,
                         c.z * inv * wv.z, c.w * inv * wv.w);
  float4 p;
  p.x = __shfl_xor_sync(0xffffffffu, n.x, 16);
  p.y = __shfl_xor_sync(0xffffffffu, n.y, 16);
  p.z = __shfl_xor_sync(0xffffffffu, n.z, 16);
  p.w = __shfl_xor_sync(0xffffffffu, n.w, 16);
  float sg = (lane < 16) ? -1.0f : 1.0f;
  float4 co = ((const float4*)(cs + (size_t)row * D_))[lane];
  float4 si = ((const float4*)(sn + (size_t)row * D_))[lane];
  float4 o;
  o.x = n.x * co.x + sg * p.x * si.x;
  o.y = n.y * co.y + sg * p.y * si.y;
  o.z = n.z * co.z + sg * p.z * si.z;
  o.w = n.w * co.w + sg * p.w * si.w;
  ((float4*)(dst + ((size_t)h * NR + row) * D_))[lane] = o;
  if (dst2) ((float4*)(dst2 + ((size_t)h * NR2 + row) * D_))[lane] = o;
}

// ---------------- v transpose (t,h,d) -> (h,t,d) ----------------
__global__ void __launch_bounds__(256) vtrans(
    const float* __restrict__ src, float* __restrict__ dst) {
  int i = blockIdx.x * 256 + threadIdx.x;
  int d4 = i & 31;
  int h = (i >> 5) & 7;
  int t = i >> 8;
  ((float4*)dst)[((size_t)h * T_ + t) * 32 + d4] = ((const float4*)src)[i];
}

// ---------------- copy cache_K -> kfull[:, 0:STATE, :] ----------------
__global__ void __launch_bounds__(256) copy_cacheK(
    const float* __restrict__ src, float* __restrict__ dst) {
  int i = blockIdx.x * 256 + threadIdx.x;
  const int PH = STATE_ * (D_ / 4);
  int h = i / PH, rem = i - h * PH;
  ((float4*)dst)[(size_t)h * S_ * (D_ / 4) + rem] = ((const float4*)src)[i];
}

// ---------------- transpose (h,s,d) -> (h,d,S) at s-offset so ----------------
__global__ void __launch_bounds__(256) transpose_hd(
    const float* __restrict__ src, float* __restrict__ dst, int ns, int so) {
  __shared__ float t[32][33];
  int h = blockIdx.z, d0 = blockIdx.y * 32, s0 = blockIdx.x * 32;
  int tx = threadIdx.x & 31, ty = threadIdx.x >> 5;
  const float* sp = src + ((size_t)h * ns + s0) * D_ + d0;
#pragma unroll
  for (int j = 0; j < 32; j += 8) t[ty + j][tx] = sp[(size_t)(ty + j) * D_ + tx];
  __syncthreads();
  float* dp = dst + ((size_t)h * D_ + d0) * S_ + so + s0;
#pragma unroll
  for (int j = 0; j < 32; j += 8) dp[(size_t)(ty + j) * S_ + tx] = t[tx][ty + j];
}

// ---------------- masked scaled softmax over S ----------------
__global__ void __launch_bounds__(256) softmax_mask(float* __restrict__ Sc) {
  const int rid = blockIdx.x;
  const int l = rid & (L_ - 1);
  const int allowed = STATE_ + CTX_ + l + 1;
  float* row = Sc + (size_t)rid * S_;
  const int t = threadIdx.x;
  float v[16];
  float mx = -INFINITY;
#pragma unroll
  for (int i = 0; i < 16; i++) {
    int idx = t + 256 * i;
    float x = (idx < allowed) ? row[idx] * SCALE_ : -INFINITY;
    v[i] = x;
    mx = fmaxf(mx, x);
  }
  __shared__ float red[8];
  int lane = t & 31, wid = t >> 5;
#pragma unroll
  for (int o = 16; o; o >>= 1) mx = fmaxf(mx, __shfl_xor_sync(0xffffffffu, mx, o));
  if (lane == 0) red[wid] = mx;
  __syncthreads();
  mx = red[0];
#pragma unroll
  for (int wi = 1; wi < 8; wi++) mx = fmaxf(mx, red[wi]);
  __syncthreads();
  float sum = 0.f;
#pragma unroll
  for (int i = 0; i < 16; i++) {
    float e = (v[i] > -INFINITY) ? __expf(v[i] - mx) : 0.f;
    v[i] = e;
    sum += e;
  }
#pragma unroll
  for (int o = 16; o; o >>= 1) sum += __shfl_xor_sync(0xffffffffu, sum, o);
  if (lane == 0) red[wid] = sum;
  __syncthreads();
  sum = red[0] + red[1] + red[2] + red[3] + red[4] + red[5] + red[6] + red[7];
  float inv = 1.f / sum;
#pragma unroll
  for (int i = 0; i < 16; i++) row[t + 256 * i] = v[i] * inv;
}

// ---------------- host launcher ----------------
extern "C" void kernel_launch(void* const* d_in, const int* in_sizes, int n_in,
                              void* d_out, int out_size) {
  const float* x    = (const float*)d_in[0];
  const float* xctx = (const float*)d_in[1];
  const float* cosq = (const float*)d_in[2];
  const float* sinq = (const float*)d_in[3];
  const float* cosk = (const float*)d_in[4];
  const float* sink = (const float*)d_in[5];
  const float* cK   = (const float*)d_in[6];
  const float* cV   = (const float*)d_in[7];
  const float* Wq   = (const float*)d_in[9];
  const float* Wk   = (const float*)d_in[10];
  const float* Wv   = (const float*)d_in[11];
  const float* Wo   = (const float*)d_in[12];
  const float* qw   = (const float*)d_in[13];
  const float* kw   = (const float*)d_in[14];

  float* out   = (float*)d_out;
  float* k_out = out + (size_t)L_ * HID_;
  float* v_out = k_out + (size_t)HKV_ * T_ * D_;

  float *pc, *pq, *pqf, *pkraw, *pvraw, *pkfull, *pvt, *psc, *po, *pt;
  cudaGetSymbolAddress((void**)&pc, g_c);
  cudaGetSymbolAddress((void**)&pq, g_q);
  cudaGetSymbolAddress((void**)&pqf, g_qf);
  cudaGetSymbolAddress((void**)&pkraw, g_kraw);
  cudaGetSymbolAddress((void**)&pvraw, g_vraw);
  cudaGetSymbolAddress((void**)&pkfull, g_kfull);
  cudaGetSymbolAddress((void**)&pvt, g_vt);
  cudaGetSymbolAddress((void**)&psc, g_scores);
  cudaGetSymbolAddress((void**)&po, g_o);
  cudaGetSymbolAddress((void**)&pt, g_part);

  cudaFuncSetAttribute(gemm4, cudaFuncAttributeMaxDynamicSharedMemorySize, GEMM_SMEM);

  // 1. c = [x_ctx; x]
  concat_c<<<T_ * HID_ / 4 / 256, 256>>>(xctx, x, pc);

  // 2. projections
  // Q: M=128,N=4096,K=4096, KS=8 -> grid 256
  gemm4<<<dim3(HID_ / BN, 1, 8), 256, GEMM_SMEM>>>(
      x, HID_, 0, Wq, HID_, 0, 0, pt, HID_, (long long)L_ * HID_, HID_, 8);
  reduce_ks<<<L_ * HID_ / 4 / 256, 256>>>(pt, pq, HID_, 0, L_, HID_, 8);
  // K: M=1024,N=1024,K=4096, KS=4 -> grid 256
  gemm4<<<dim3(HKV_ * D_ / BN, T_ / BM, 4), 256, GEMM_SMEM>>>(
      pc, HID_, 0, Wk, HID_, 0, 0, pt, HKV_ * D_, (long long)T_ * HKV_ * D_, HID_, 4);
  reduce_ks<<<T_ * HKV_ * D_ / 4 / 256, 256>>>(pt, pkraw, HKV_ * D_, 0, T_, HKV_ * D_, 4);
  // V
  gemm4<<<dim3(HKV_ * D_ / BN, T_ / BM, 4), 256, GEMM_SMEM>>>(
      pc, HID_, 0, Wv, HID_, 0, 0, pt, HKV_ * D_, (long long)T_ * HKV_ * D_, HID_, 4);
  reduce_ks<<<T_ * HKV_ * D_ / 4 / 256, 256>>>(pt, pvraw, HKV_ * D_, 0, T_, HKV_ * D_, 4);

  // 3. norm + rope, v transpose
  norm_rope<<<(L_ * HQ_) / 4, 128>>>(pq, qw, cosq, sinq, pqf, HQ_, L_, nullptr, 0);
  norm_rope<<<(T_ * HKV_) / 4, 128>>>(pkraw, kw, cosk, sink, k_out, HKV_, T_,
                                      pkfull + (size_t)STATE_ * D_, S_);
  vtrans<<<T_ * HKV_ * D_ / 4 / 256, 256>>>(pvraw, v_out);

  // 4. assemble full K / V^T
  copy_cacheK<<<HKV_ * STATE_ * (D_ / 4) / 256, 256>>>(cK, pkfull);
  transpose_hd<<<dim3(STATE_ / 32, D_ / 32, HKV_), 256>>>(cV, pvt, STATE_, 0);
  transpose_hd<<<dim3(T_ / 32, D_ / 32, HKV_), 256>>>(v_out, pvt, T_, STATE_);

  // 5. attention
  // scores: per head M=128,N=4096,K=128 -> grid (32,1,32)
  gemm4<<<dim3(S_ / BN, 1, HQ_), 256, GEMM_SMEM>>>(
      pqf, D_, (long long)L_ * D_,
      pkfull, D_, (long long)S_ * D_, 2,
      psc, S_, (long long)L_ * S_, D_, 1);
  softmax_mask<<<HQ_ * L_, 256>>>(psc);
  // PV: per head M=128,N=128,K=4096, KS=8 -> grid 256
  gemm4<<<dim3(D_ / BN, 1, HQ_ * 8), 256, GEMM_SMEM>>>(
      psc, S_, (long long)L_ * S_,
      pvt, S_, (long long)D_ * S_, 2,
      pt, D_, (long long)L_ * D_, S_, 8);
  reduce_ks<<<HQ_ * L_ * D_ / 4 / 256, 256>>>(pt, po, HQ_ * D_, D_, L_, D_, 8);

  // 6. output projection: M=128,N=4096,K=4096, KS=8
  gemm4<<<dim3(HID_ / BN, 1, 8), 256, GEMM_SMEM>>>(
      po, HQ_ * D_, 0, Wo, HQ_ * D_, 0, 0, pt, HID_, (long long)L_ * HID_, HQ_ * D_, 8);
  reduce_ks<<<L_ * HID_ / 4 / 256, 256>>>(pt, out, HID_, 0, L_, HID_, 8);

  (void)in_sizes; (void)n_in; (void)out_size;
}

// round 9
// speedup vs baseline: 1.1353x; 1.1353x over previous
#include <cuda_runtime.h>
#include <cuda_bf16.h>
#include <math.h>
#include <stdint.h>

// Problem constants
#define L_     128
#define CTX_   896
#define T_     1024
#define STATE_ 3072
#define S_     4096
#define HID_   4096
#define HQ_    32
#define HKV_   8
#define D_     128
#define EPS_   1e-6f
#define SCALE_ 0.08838834764831845f   // 128^-0.5

// GEMM tiling
#define BM 128
#define BN 128
#define BK 32
#define NSTAGE 3
#define GSTR 40                         // bf16 smem row stride in halves (80B)
#define TILE_H (128 * GSTR)             // halves per 128x32 tile = 5120
#define STG_H  (4 * TILE_H)             // aHi,aLo,bHi,bLo = 20480 halves
#define STG_B  (STG_H * 2)              // 40960 bytes
#define SM_OPER 1024
#define GEMM_SMEM (SM_OPER + NSTAGE * STG_B)   // 123904 bytes

// ---------------- device scratch ----------------
__device__ float g_c[T_ * HID_];
__device__ float g_q[L_ * HQ_ * D_];
__device__ float g_qf[HQ_ * L_ * D_];
__device__ float g_kraw[T_ * HKV_ * D_];
__device__ float g_vraw[T_ * HKV_ * D_];
__device__ float g_kfull[HKV_ * S_ * D_];
__device__ float g_vt[HKV_ * D_ * S_];
__device__ float g_scores[(size_t)HQ_ * L_ * S_];
__device__ float g_o[L_ * HQ_ * D_];
__device__ float g_part[4 * 1024 * 1024];

// ---------------- helpers ----------------
__device__ __forceinline__ uint32_t smem_u32(const void* p) {
  return (uint32_t)__cvta_generic_to_shared(p);
}
__device__ __forceinline__ void ldm_x4(uint32_t (&r)[4], uint32_t addr) {
  asm volatile("ldmatrix.sync.aligned.m8n8.x4.shared.b16 {%0,%1,%2,%3}, [%4];\n"
    : "=r"(r[0]), "=r"(r[1]), "=r"(r[2]), "=r"(r[3]) : "r"(addr));
}
__device__ __forceinline__ void mma16816(float (&d)[4], const uint32_t (&a)[4],
                                         uint32_t b0, uint32_t b1) {
  asm volatile("mma.sync.aligned.m16n8k16.row.col.f32.bf16.bf16.f32 "
    "{%0,%1,%2,%3},{%4,%5,%6,%7},{%8,%9},{%0,%1,%2,%3};\n"
    : "+f"(d[0]), "+f"(d[1]), "+f"(d[2]), "+f"(d[3])
    : "r"(a[0]), "r"(a[1]), "r"(a[2]), "r"(a[3]), "r"(b0), "r"(b1));
}
__device__ __forceinline__ void mbar_init(uint32_t mbar, uint32_t cnt) {
  asm volatile("mbarrier.init.shared.b64 [%0], %1;" :: "r"(mbar), "r"(cnt) : "memory");
}
__device__ __forceinline__ void mbar_arrive(uint32_t mbar) {
  asm volatile("mbarrier.arrive.shared.b64 _, [%0];" :: "r"(mbar) : "memory");
}
__device__ __forceinline__ void mbar_wait(uint32_t mbar, uint32_t phase) {
  asm volatile(
    "{\n\t.reg .pred P1;\n\t"
    "WAIT_%=:\n\t"
    "mbarrier.try_wait.parity.acquire.cta.shared::cta.b64 P1, [%0], %1, 0x989680;\n\t"
    "@P1 bra.uni DONE_%=;\n\t"
    "bra.uni WAIT_%=;\n\t"
    "DONE_%=:\n\t}"
    :: "r"(mbar), "r"(phase) : "memory");
}
// convert float4 -> hi bf16x2 pair + lo bf16x2 pair, store to smem
__device__ __forceinline__ void cvt_store(__nv_bfloat16* hi, __nv_bfloat16* lo, float4 v) {
  __nv_bfloat162 h01 = __floats2bfloat162_rn(v.x, v.y);
  __nv_bfloat162 h23 = __floats2bfloat162_rn(v.z, v.w);
  *(__nv_bfloat162*)(hi)     = h01;
  *(__nv_bfloat162*)(hi + 2) = h23;
  *(__nv_bfloat162*)(lo) = __floats2bfloat162_rn(
      v.x - __bfloat162float(h01.x), v.y - __bfloat162float(h01.y));
  *(__nv_bfloat162*)(lo + 2) = __floats2bfloat162_rn(
      v.z - __bfloat162float(h23.x), v.w - __bfloat162float(h23.y));
}

// ---------------- concat c = [x_ctx; x] ----------------
__global__ void __launch_bounds__(256) concat_c(
    const float* __restrict__ xc, const float* __restrict__ x, float* __restrict__ c) {
  int i = blockIdx.x * 256 + threadIdx.x;
  const int CV = CTX_ * HID_ / 4;
  float4 v = (i < CV) ? ((const float4*)xc)[i] : ((const float4*)x)[i - CV];
  ((float4*)c)[i] = v;
}

// ============ warp-specialized split-bf16 tensor-core GEMM (mbarrier ring) ============
// z = b*KS + ks.  C[b][M][N] = A[b][M][K] * B[b>>bshift][N][K]^T
// Warps 0-7: MMA consumers (32x64 warp tiles).  Warps 8-15: load+convert producers.
__global__ void __launch_bounds__(512) gemm6(
    const float* __restrict__ A, int lda, long long batchA,
    const float* __restrict__ B, int ldb, long long batchB, int bshift,
    float* __restrict__ C, int ldc, long long batchC,
    int K, int KS)
{
  extern __shared__ char smc[];
  const uint32_t smem_base = smem_u32(smc);
  const int tid = threadIdx.x, lane = tid & 31, wid = tid >> 5;
  const int m0 = blockIdx.y * BM, n0 = blockIdx.x * BN;
  const int b = blockIdx.z / KS, ks = blockIdx.z - b * KS;
  const int Kc = K / KS, kbase = ks * Kc, iters = Kc / BK;

  // mbarriers: full[s] at +16s, empty[s] at +16s+8
  if (tid == 0) {
#pragma unroll
    for (int s = 0; s < NSTAGE; s++) {
      mbar_init(smem_base + 16 * s, 256);
      mbar_init(smem_base + 16 * s + 8, 256);
    }
  }
  __syncthreads();

  if (wid < 8) {
    // ---------------- consumer: MMA ----------------
    const int wm = wid & 3, wn = wid >> 2;     // 4x2 warps, warp tile 32x64
    const int a_r = lane & 15, a_c = (lane & 16) >> 1;
    const int b_r = (lane & 7) | ((lane & 16) >> 1), b_c = lane & 8;

    float acc[2][8][4];
#pragma unroll
    for (int i = 0; i < 2; i++)
#pragma unroll
      for (int j = 0; j < 8; j++)
#pragma unroll
        for (int q = 0; q < 4; q++) acc[i][j][q] = 0.f;

    int stage = 0, phase = 0;
    for (int it = 0; it < iters; it++) {
      mbar_wait(smem_base + 16 * stage, phase);
      const uint32_t sb = smem_base + SM_OPER + stage * STG_B;
#pragma unroll
      for (int k16 = 0; k16 < BK; k16 += 16) {
        uint32_t aH[2][4], aL[2][4];
#pragma unroll
        for (int mi = 0; mi < 2; mi++) {
          uint32_t ro = (uint32_t)(((wm * 32 + mi * 16 + a_r) * GSTR + k16 + a_c) * 2);
          ldm_x4(aH[mi], sb + ro);
          ldm_x4(aL[mi], sb + TILE_H * 2 + ro);
        }
#pragma unroll
        for (int g = 0; g < 4; g++) {
          uint32_t bH[4], bL[4];
          uint32_t ro = (uint32_t)(((wn * 64 + g * 16 + b_r) * GSTR + k16 + b_c) * 2);
          ldm_x4(bH, sb + 2 * TILE_H * 2 + ro);
          ldm_x4(bL, sb + 3 * TILE_H * 2 + ro);
#pragma unroll
          for (int mi = 0; mi < 2; mi++)
#pragma unroll
            for (int sub = 0; sub < 2; sub++) {
              int ni = g * 2 + sub, rr = sub * 2;
              mma16816(acc[mi][ni], aH[mi], bH[rr], bH[rr + 1]);
              mma16816(acc[mi][ni], aH[mi], bL[rr], bL[rr + 1]);
              mma16816(acc[mi][ni], aL[mi], bH[rr], bH[rr + 1]);
            }
        }
      }
      mbar_arrive(smem_base + 16 * stage + 8);
      if (++stage == NSTAGE) { stage = 0; phase ^= 1; }
    }
    // epilogue
    float* Cb = (KS == 1) ? C + (long long)b * batchC : C + (long long)blockIdx.z * batchC;
    const int rb8 = lane >> 2, cb2 = (lane & 3) << 1;
#pragma unroll
    for (int mi = 0; mi < 2; mi++)
#pragma unroll
      for (int ni = 0; ni < 8; ni++) {
        int row = m0 + wm * 32 + mi * 16 + rb8;
        int col = n0 + wn * 64 + ni * 8 + cb2;
        *(float2*)(Cb + (long long)row * ldc + col)       = make_float2(acc[mi][ni][0], acc[mi][ni][1]);
        *(float2*)(Cb + (long long)(row + 8) * ldc + col) = make_float2(acc[mi][ni][2], acc[mi][ni][3]);
      }
  } else {
    // ---------------- producer: load + convert ----------------
    const int p = tid - 256;                   // 0..255
    const int lrow = p >> 3, lcol4 = p & 7;
    const float* Ag = A + (long long)b * batchA + (size_t)(m0 + lrow) * lda + kbase + (lcol4 << 2);
    const float* Bg = B + (long long)(b >> bshift) * batchB + (size_t)(n0 + lrow) * ldb + kbase + (lcol4 << 2);

    float4 ra[4], rb[4];
#pragma unroll
    for (int j = 0; j < 4; j++) ra[j] = *(const float4*)(Ag + (size_t)(32 * j) * lda);
#pragma unroll
    for (int j = 0; j < 4; j++) rb[j] = *(const float4*)(Bg + (size_t)(32 * j) * ldb);

    int stage = 0, phase = 1;
    for (int it = 0; it < iters; it++) {
      mbar_wait(smem_base + 16 * stage + 8, phase);
      __nv_bfloat16* st = (__nv_bfloat16*)(smc + SM_OPER) + stage * STG_H;
#pragma unroll
      for (int j = 0; j < 4; j++) {
        int off = (lrow + 32 * j) * GSTR + (lcol4 << 2);
        cvt_store(st + off,              st + TILE_H + off,     ra[j]);
        cvt_store(st + 2 * TILE_H + off, st + 3 * TILE_H + off, rb[j]);
      }
      mbar_arrive(smem_base + 16 * stage);
      if (++stage == NSTAGE) { stage = 0; phase ^= 1; }
      if (it + 1 < iters) {
        const float* An = Ag + (it + 1) * BK;
        const float* Bn = Bg + (it + 1) * BK;
#pragma unroll
        for (int j = 0; j < 4; j++) ra[j] = *(const float4*)(An + (size_t)(32 * j) * lda);
#pragma unroll
        for (int j = 0; j < 4; j++) rb[j] = *(const float4*)(Bn + (size_t)(32 * j) * ldb);
      }
    }
  }
}

// ---------------- split-K reduction ----------------
__global__ void __launch_bounds__(256) reduce_ks(
    const float* __restrict__ Pt, float* __restrict__ out,
    int ldc, long long batchC, int M, int N, int KS) {
  long long i4 = (long long)blockIdx.x * 256 + threadIdx.x;
  int perB = M * (N >> 2);
  int b = (int)(i4 / perB);
  int rem = (int)(i4 - (long long)b * perB);
  int m = rem / (N >> 2), n4 = rem - m * (N >> 2);
  const float4* base = (const float4*)Pt + (long long)b * KS * perB + rem;
  float4 s = base[0];
  for (int k = 1; k < KS; k++) {
    float4 v = base[(long long)k * perB];
    s.x += v.x; s.y += v.y; s.z += v.z; s.w += v.w;
  }
  *(float4*)(out + (long long)b * batchC + (long long)m * ldc + (n4 << 2)) = s;
}

// ---------------- fused ane-norm + RoPE ----------------
__global__ void __launch_bounds__(128) norm_rope(
    const float* __restrict__ src, const float* __restrict__ w,
    const float* __restrict__ cs, const float* __restrict__ sn,
    float* __restrict__ dst, int NH, int NR,
    float* __restrict__ dst2, int NR2) {
  int r = blockIdx.x * 4 + (threadIdx.x >> 5);
  int lane = threadIdx.x & 31;
  int row = r / NH, h = r - row * NH;
  float4 v = ((const float4*)(src + (size_t)r * D_))[lane];
  float s = v.x + v.y + v.z + v.w;
#pragma unroll
  for (int o = 16; o; o >>= 1) s += __shfl_xor_sync(0xffffffffu, s, o);
  float mean = s * (1.0f / D_);
  float4 c = make_float4(v.x - mean, v.y - mean, v.z - mean, v.w - mean);
  float q2 = c.x * c.x + c.y * c.y + c.z * c.z + c.w * c.w;
#pragma unroll
  for (int o = 16; o; o >>= 1) q2 += __shfl_xor_sync(0xffffffffu, q2, o);
  float inv = rsqrtf(q2 * (1.0f / D_) + EPS_);
  float4 wv = ((const float4*)w)[lane];
  float4 n = make_float4(c.x * inv * wv.x, c.y * inv * wv.y,
                         c.z * inv * wv.z, c.w * inv * wv.w);
  float4 p;
  p.x = __shfl_xor_sync(0xffffffffu, n.x, 16);
  p.y = __shfl_xor_sync(0xffffffffu, n.y, 16);
  p.z = __shfl_xor_sync(0xffffffffu, n.z, 16);
  p.w = __shfl_xor_sync(0xffffffffu, n.w, 16);
  float sg = (lane < 16) ? -1.0f : 1.0f;
  float4 co = ((const float4*)(cs + (size_t)row * D_))[lane];
  float4 si = ((const float4*)(sn + (size_t)row * D_))[lane];
  float4 o;
  o.x = n.x * co.x + sg * p.x * si.x;
  o.y = n.y * co.y + sg * p.y * si.y;
  o.z = n.z * co.z + sg * p.z * si.z;
  o.w = n.w * co.w + sg * p.w * si.w;
  ((float4*)(dst + ((size_t)h * NR + row) * D_))[lane] = o;
  if (dst2) ((float4*)(dst2 + ((size_t)h * NR2 + row) * D_))[lane] = o;
}

// ---------------- v transpose (t,h,d) -> (h,t,d) ----------------
__global__ void __launch_bounds__(256) vtrans(
    const float* __restrict__ src, float* __restrict__ dst) {
  int i = blockIdx.x * 256 + threadIdx.x;
  int d4 = i & 31;
  int h = (i >> 5) & 7;
  int t = i >> 8;
  ((float4*)dst)[((size_t)h * T_ + t) * 32 + d4] = ((const float4*)src)[i];
}

// ---------------- copy cache_K -> kfull[:, 0:STATE, :] ----------------
__global__ void __launch_bounds__(256) copy_cacheK(
    const float* __restrict__ src, float* __restrict__ dst) {
  int i = blockIdx.x * 256 + threadIdx.x;
  const int PH = STATE_ * (D_ / 4);
  int h = i / PH, rem = i - h * PH;
  ((float4*)dst)[(size_t)h * S_ * (D_ / 4) + rem] = ((const float4*)src)[i];
}

// ---------------- transpose (h,s,d) -> (h,d,S) at s-offset so ----------------
__global__ void __launch_bounds__(256) transpose_hd(
    const float* __restrict__ src, float* __restrict__ dst, int ns, int so) {
  __shared__ float t[32][33];
  int h = blockIdx.z, d0 = blockIdx.y * 32, s0 = blockIdx.x * 32;
  int tx = threadIdx.x & 31, ty = threadIdx.x >> 5;
  const float* sp = src + ((size_t)h * ns + s0) * D_ + d0;
#pragma unroll
  for (int j = 0; j < 32; j += 8) t[ty + j][tx] = sp[(size_t)(ty + j) * D_ + tx];
  __syncthreads();
  float* dp = dst + ((size_t)h * D_ + d0) * S_ + so + s0;
#pragma unroll
  for (int j = 0; j < 32; j += 8) dp[(size_t)(ty + j) * S_ + tx] = t[tx][ty + j];
}

// ---------------- masked scaled softmax over S ----------------
__global__ void __launch_bounds__(256) softmax_mask(float* __restrict__ Sc) {
  const int rid = blockIdx.x;
  const int l = rid & (L_ - 1);
  const int allowed = STATE_ + CTX_ + l + 1;
  float* row = Sc + (size_t)rid * S_;
  const int t = threadIdx.x;
  float v[16];
  float mx = -INFINITY;
#pragma unroll
  for (int i = 0; i < 16; i++) {
    int idx = t + 256 * i;
    float x = (idx < allowed) ? row[idx] * SCALE_ : -INFINITY;
    v[i] = x;
    mx = fmaxf(mx, x);
  }
  __shared__ float red[8];
  int lane = t & 31, wid = t >> 5;
#pragma unroll
  for (int o = 16; o; o >>= 1) mx = fmaxf(mx, __shfl_xor_sync(0xffffffffu, mx, o));
  if (lane == 0) red[wid] = mx;
  __syncthreads();
  mx = red[0];
#pragma unroll
  for (int wi = 1; wi < 8; wi++) mx = fmaxf(mx, red[wi]);
  __syncthreads();
  float sum = 0.f;
#pragma unroll
  for (int i = 0; i < 16; i++) {
    float e = (v[i] > -INFINITY) ? __expf(v[i] - mx) : 0.f;
    v[i] = e;
    sum += e;
  }
#pragma unroll
  for (int o = 16; o; o >>= 1) sum += __shfl_xor_sync(0xffffffffu, sum, o);
  if (lane == 0) red[wid] = sum;
  __syncthreads();
  sum = red[0] + red[1] + red[2] + red[3] + red[4] + red[5] + red[6] + red[7];
  float inv = 1.f / sum;
#pragma unroll
  for (int i = 0; i < 16; i++) row[t + 256 * i] = v[i] * inv;
}

// ---------------- host launcher ----------------
extern "C" void kernel_launch(void* const* d_in, const int* in_sizes, int n_in,
                              void* d_out, int out_size) {
  const float* x    = (const float*)d_in[0];
  const float* xctx = (const float*)d_in[1];
  const float* cosq = (const float*)d_in[2];
  const float* sinq = (const float*)d_in[3];
  const float* cosk = (const float*)d_in[4];
  const float* sink = (const float*)d_in[5];
  const float* cK   = (const float*)d_in[6];
  const float* cV   = (const float*)d_in[7];
  const float* Wq   = (const float*)d_in[9];
  const float* Wk   = (const float*)d_in[10];
  const float* Wv   = (const float*)d_in[11];
  const float* Wo   = (const float*)d_in[12];
  const float* qw   = (const float*)d_in[13];
  const float* kw   = (const float*)d_in[14];

  float* out   = (float*)d_out;
  float* k_out = out + (size_t)L_ * HID_;
  float* v_out = k_out + (size_t)HKV_ * T_ * D_;

  float *pc, *pq, *pqf, *pkraw, *pvraw, *pkfull, *pvt, *psc, *po, *pt;
  cudaGetSymbolAddress((void**)&pc, g_c);
  cudaGetSymbolAddress((void**)&pq, g_q);
  cudaGetSymbolAddress((void**)&pqf, g_qf);
  cudaGetSymbolAddress((void**)&pkraw, g_kraw);
  cudaGetSymbolAddress((void**)&pvraw, g_vraw);
  cudaGetSymbolAddress((void**)&pkfull, g_kfull);
  cudaGetSymbolAddress((void**)&pvt, g_vt);
  cudaGetSymbolAddress((void**)&psc, g_scores);
  cudaGetSymbolAddress((void**)&po, g_o);
  cudaGetSymbolAddress((void**)&pt, g_part);

  cudaFuncSetAttribute(gemm6, cudaFuncAttributeMaxDynamicSharedMemorySize, GEMM_SMEM);

  // 1. c = [x_ctx; x]
  concat_c<<<T_ * HID_ / 4 / 256, 256>>>(xctx, x, pc);

  // 2. projections
  // Q: M=128,N=4096,K=4096, KS=4 -> 128 blocks
  gemm6<<<dim3(HID_ / BN, 1, 4), 512, GEMM_SMEM>>>(
      x, HID_, 0, Wq, HID_, 0, 0, pt, HID_, (long long)L_ * HID_, HID_, 4);
  reduce_ks<<<L_ * HID_ / 4 / 256, 256>>>(pt, pq, HID_, 0, L_, HID_, 4);
  // K: M=1024,N=1024,K=4096, KS=2 -> 128 blocks
  gemm6<<<dim3(HKV_ * D_ / BN, T_ / BM, 2), 512, GEMM_SMEM>>>(
      pc, HID_, 0, Wk, HID_, 0, 0, pt, HKV_ * D_, (long long)T_ * HKV_ * D_, HID_, 2);
  reduce_ks<<<T_ * HKV_ * D_ / 4 / 256, 256>>>(pt, pkraw, HKV_ * D_, 0, T_, HKV_ * D_, 2);
  // V
  gemm6<<<dim3(HKV_ * D_ / BN, T_ / BM, 2), 512, GEMM_SMEM>>>(
      pc, HID_, 0, Wv, HID_, 0, 0, pt, HKV_ * D_, (long long)T_ * HKV_ * D_, HID_, 2);
  reduce_ks<<<T_ * HKV_ * D_ / 4 / 256, 256>>>(pt, pvraw, HKV_ * D_, 0, T_, HKV_ * D_, 2);

  // 3. norm + rope, v transpose
  norm_rope<<<(L_ * HQ_) / 4, 128>>>(pq, qw, cosq, sinq, pqf, HQ_, L_, nullptr, 0);
  norm_rope<<<(T_ * HKV_) / 4, 128>>>(pkraw, kw, cosk, sink, k_out, HKV_, T_,
                                      pkfull + (size_t)STATE_ * D_, S_);
  vtrans<<<T_ * HKV_ * D_ / 4 / 256, 256>>>(pvraw, v_out);

  // 4. assemble full K / V^T
  copy_cacheK<<<HKV_ * STATE_ * (D_ / 4) / 256, 256>>>(cK, pkfull);
  transpose_hd<<<dim3(STATE_ / 32, D_ / 32, HKV_), 256>>>(cV, pvt, STATE_, 0);
  transpose_hd<<<dim3(T_ / 32, D_ / 32, HKV_), 256>>>(v_out, pvt, T_, STATE_);

  // 5. attention
  // scores: per head M=128,N=4096,K=128, KS=1
  gemm6<<<dim3(S_ / BN, 1, HQ_), 512, GEMM_SMEM>>>(
      pqf, D_, (long long)L_ * D_,
      pkfull, D_, (long long)S_ * D_, 2,
      psc, S_, (long long)L_ * S_, D_, 1);
  softmax_mask<<<HQ_ * L_, 256>>>(psc);
  // PV: per head M=128,N=128,K=4096, KS=4 -> 128 blocks
  gemm6<<<dim3(D_ / BN, 1, HQ_ * 4), 512, GEMM_SMEM>>>(
      psc, S_, (long long)L_ * S_,
      pvt, S_, (long long)D_ * S_, 2,
      pt, D_, (long long)L_ * D_, S_, 4);
  reduce_ks<<<HQ_ * L_ * D_ / 4 / 256, 256>>>(pt, po, HQ_ * D_, D_, L_, D_, 4);

  // 6. output projection: M=128,N=4096,K=4096, KS=4
  gemm6<<<dim3(HID_ / BN, 1, 4), 512, GEMM_SMEM>>>(
      po, HQ_ * D_, 0, Wo, HQ_ * D_, 0, 0, pt, HID_, (long long)L_ * HID_, HQ_ * D_, 4);
  reduce_ks<<<L_ * HID_ / 4 / 256, 256>>>(pt, out, HID_, 0, L_, HID_, 4);

  (void)in_sizes; (void)n_in; (void)out_size;
}